// round 9
// baseline (speedup 1.0000x reference)
#include <cuda_runtime.h>
#include <cstdint>

// ---------------------------------------------------------------------------
// Problem constants
// ---------------------------------------------------------------------------
#define N_ROWS 16384      // 64 * 256
#define N_FEAT 2048
#define N_BINS 32
#define NSTRIPE 512
#define RPS (N_ROWS / NSTRIPE)     // 32 rows per stripe
#define TBL 65536
#define NTILE 128                  // 128-row tiles
#define NKQ 4                      // K split into quarters (512 cols each)
#define NG 64                      // 32-col groups over full K
#define NT16 (N_ROWS / 16)         // 1024 16-row fragments
// k_project dynamic smem: RP quarter 16KB + A block 64KB + soff
#define PROJ_SMEM (16384 + 65536 + 128)

// ---------------------------------------------------------------------------
// Scratch (static device globals; no runtime allocation)
// ---------------------------------------------------------------------------
__device__ __align__(16) unsigned int g_xpack8[(size_t)NT16 * NG * 32 * 4]; // e4m3 x (32MB)
__device__ float              g_psum[NSTRIPE * N_FEAT];
__device__ float              g_psq [NSTRIPE * N_FEAT];
__device__ float              g_isig[N_FEAT];
__device__ float              g_m2  [N_FEAT];              // mean * isig
__device__ float              g_off [N_BINS];              // 256 * (m2 . RP)
__device__ __align__(16) unsigned int g_rppack8[512 * 32]; // e4m3x4 256*isig*RP, swizzled
__device__ float              g_part[NKQ * N_ROWS * N_BINS]; // split-K partials
__device__ unsigned int       g_tilecnt[NTILE];            // arrival counters
__device__ unsigned int       g_hash[N_ROWS];
__device__ unsigned int       g_slot[N_ROWS];
__device__ unsigned long long g_tkey[TBL];
__device__ unsigned int       g_tcnt[TBL];

// ---------------------------------------------------------------------------
// Helpers
// ---------------------------------------------------------------------------
__device__ __forceinline__ unsigned pack8x4(float f0, float f1, float f2, float f3) {
    unsigned d;
    asm("{\n\t"
        ".reg .b16 lo, hi;\n\t"
        "cvt.rn.satfinite.e4m3x2.f32 lo, %2, %1;\n\t"
        "cvt.rn.satfinite.e4m3x2.f32 hi, %4, %3;\n\t"
        "mov.b32 %0, {lo, hi};\n\t"
        "}" : "=r"(d) : "f"(f0), "f"(f1), "f"(f2), "f"(f3));
    return d;
}

__device__ __forceinline__ void mma16832(float* c,
                                         unsigned a0, unsigned a1, unsigned a2, unsigned a3,
                                         unsigned b0, unsigned b1) {
    asm volatile(
        "mma.sync.aligned.m16n8k32.row.col.f32.e4m3.e4m3.f32 "
        "{%0,%1,%2,%3}, {%4,%5,%6,%7}, {%8,%9}, {%0,%1,%2,%3};"
        : "+f"(c[0]), "+f"(c[1]), "+f"(c[2]), "+f"(c[3])
        : "r"(a0), "r"(a1), "r"(a2), "r"(a3), "r"(b0), "r"(b1));
}

__device__ __forceinline__ uint32_t smaddr(const void* p) {
    return (uint32_t)__cvta_generic_to_shared(p);
}

__device__ __forceinline__ void cpa16(uint32_t dst, const void* src) {
    asm volatile("cp.async.cg.shared.global [%0], [%1], 16;" :: "r"(dst), "l"(src));
}

__device__ __forceinline__ void table_insert(int i, unsigned h) {
    unsigned long long key = ((unsigned long long)h << 6) | (unsigned long long)(i & 63);
    unsigned long long m = key * 0x9E3779B97F4A7C15ULL;
    unsigned s = (unsigned)(m >> 48);   // 16-bit slot
    for (;;) {
        unsigned long long prev = atomicCAS(&g_tkey[s], ~0ULL, key);
        if (prev == ~0ULL || prev == key) {
            atomicAdd(&g_tcnt[s], 1u);
            g_slot[i] = s;
            return;
        }
        s = (s + 1) & (TBL - 1);
    }
}

// ---------------------------------------------------------------------------
// Kernel 1 (fused): column partial sums + e4m3 fragment-order pack + inits.
//   blocks [0,1024): stats+pack (512 stripes x 32 rows, 2 col-halves).
//   blocks [1024,1280): hash-table / counter init.
// Fragment layout (m16n8k32 A): word addr =
//   ((tile16*NG + g)*32 + (rr*4 + qp))*4 + ((khalf<<1) | half8)
// ---------------------------------------------------------------------------
__global__ void k_pre(const float* __restrict__ x) {
    int b = blockIdx.x;
    if (b < 1024) {
        int colblk = b & 1, stripe = b >> 1;          // 512 stripes x 32 rows
        int P4 = colblk * 256 + threadIdx.x;          // word index 0..511
        int g = P4 >> 3, qp = P4 & 3, khalf = (P4 >> 2) & 1;
        int row0 = stripe * RPS;
        const float4* src = (const float4*)x + (size_t)row0 * 512 + P4;
        float s0 = 0.f, s1 = 0.f, s2 = 0.f, s3 = 0.f;
        float q0 = 0.f, q1 = 0.f, q2 = 0.f, q3 = 0.f;
#pragma unroll 8
        for (int r = 0; r < RPS; r++) {
            int row = row0 + r;
            float4 v = src[(size_t)r * 512];
            s0 += v.x; q0 = fmaf(v.x, v.x, q0);
            s1 += v.y; q1 = fmaf(v.y, v.y, q1);
            s2 += v.z; q2 = fmaf(v.z, v.z, q2);
            s3 += v.w; q3 = fmaf(v.w, v.w, q3);
            int tile16 = row >> 4, half8 = (row >> 3) & 1, rr = row & 7;
            size_t addr = (((size_t)tile16 * NG + g) * 32 + (rr * 4 + qp)) * 4
                          + ((khalf << 1) | half8);
            g_xpack8[addr] = pack8x4(v.x, v.y, v.z, v.w);
        }
        *(float4*)(g_psum + stripe * N_FEAT + 4 * P4) = make_float4(s0, s1, s2, s3);
        *(float4*)(g_psq  + stripe * N_FEAT + 4 * P4) = make_float4(q0, q1, q2, q3);
    } else {
        int i = (b - 1024) * 256 + threadIdx.x;
        g_tkey[i] = ~0ULL;
        g_tcnt[i] = 0u;
        if (b == 1024 && threadIdx.x < NTILE) g_tilecnt[threadIdx.x] = 0u;
    }
}

// ---------------------------------------------------------------------------
// Kernel 2: finalize RunningMeanStd -> isig, mean*isig
// ---------------------------------------------------------------------------
__global__ void k_stats() {
    __shared__ float ss[8][32], sq[8][32];
    int c = threadIdx.x & 31, g = threadIdx.x >> 5;
    int col = blockIdx.x * 32 + c;
    float s = 0.f, q = 0.f;
    for (int st = g; st < NSTRIPE; st += 8) {
        s += g_psum[st * N_FEAT + col];
        q += g_psq [st * N_FEAT + col];
    }
    ss[g][c] = s; sq[g][c] = q;
    __syncthreads();
    if (g == 0) {
#pragma unroll
        for (int j = 1; j < 8; j++) { s += ss[j][c]; q += sq[j][c]; }
        const float n = 16384.0f;
        float bm = s / n;
        float bv = (q - bm * bm * n) / (n - 1.0f);       // unbiased variance
        const double nd = 16384.0, totd = 1e-4 + nd;
        float mean = bm * (float)(nd / totd);
        float m2v  = (1e-4f + bv * 16384.0f) + (bm * bm) * (float)(1e-4 * nd / totd);
        float var  = m2v / (float)totd;
        float isg  = 1.0f / sqrtf(var + 1e-8f);
        g_isig[col] = isg;
        g_m2[col]   = mean * isg;
    }
}

// ---------------------------------------------------------------------------
// Kernel 3: RP'' = 256*isig*RP packed e4m3x4 swizzled (blocks 0..63);
//           off[b] = 256 * sum_k m2[k]*RP[k,b] (block 64, deterministic).
// ---------------------------------------------------------------------------
__global__ void k_scale(const float* __restrict__ rp) {
    if (blockIdx.x < 64) {
        int idx = blockIdx.x * 256 + threadIdx.x;  // 0..16383
        int k4 = idx >> 5;                         // 4-col k word 0..511
        int n  = idx & 31;
        float f0 = rp[(4 * k4 + 0) * N_BINS + n] * g_isig[4 * k4 + 0] * 256.0f;
        float f1 = rp[(4 * k4 + 1) * N_BINS + n] * g_isig[4 * k4 + 1] * 256.0f;
        float f2 = rp[(4 * k4 + 2) * N_BINS + n] * g_isig[4 * k4 + 2] * 256.0f;
        float f3 = rp[(4 * k4 + 3) * N_BINS + n] * g_isig[4 * k4 + 3] * 256.0f;
        int scol = n ^ ((k4 & 3) << 3);
        g_rppack8[k4 * 32 + scol] = pack8x4(f0, f1, f2, f3);
    } else {
        __shared__ float red[8][32];
        int b = threadIdx.x & 31, part = threadIdx.x >> 5;   // 8 parts x 256 k
        float s = 0.f;
        for (int k = part * 256; k < part * 256 + 256; k++)
            s = fmaf(g_m2[k], rp[k * N_BINS + b], s);
        red[part][b] = s;
        __syncthreads();
        if (part == 0) {
#pragma unroll
            for (int j = 1; j < 8; j++) s += red[j][b];
            g_off[b] = s * 256.0f;
        }
    }
}

// ---------------------------------------------------------------------------
// Kernel 4: quarter-K e4m3 mma projection. cp.async stages the block's whole
// A working set (64KB) + RP quarter (16KB) into smem -> LDS.128 mainloop ->
// fp32 partials -> (last-arriving quarter per tile) combine + sign + insert.
//   512 blocks: tile = bid>>2 (128 rows), kq = bid&3.
// ---------------------------------------------------------------------------
__global__ void __launch_bounds__(256, 2) k_project() {
    extern __shared__ unsigned smem[];
    unsigned* srp = smem;                        // [0,4096) words: RP quarter
    unsigned* sa  = smem + 4096;                 // [4096,20480) words: A 64KB
    float* soff   = (float*)(smem + 20480);      // [32]
    __shared__ int s_last;

    int tile = blockIdx.x >> 2;
    int kq   = blockIdx.x & 3;
    int tid  = threadIdx.x;

    // stage RP quarter (1024 x 16B) via cp.async
    {
        const char* src = (const char*)(g_rppack8 + kq * 4096);
        uint32_t dst = smaddr(srp);
#pragma unroll
        for (int i = 0; i < 4; i++) {
            int idx = tid + i * 256;
            cpa16(dst + idx * 16, src + idx * 16);
        }
    }
    // stage A block (4096 x 16B): warp w's tile16 chunk is 8KB contiguous
    {
        uint32_t dst = smaddr(sa);
#pragma unroll
        for (int i = 0; i < 16; i++) {
            int idx = tid + i * 256;          // 0..4095 (16B units)
            int w = idx >> 9, inner = idx & 511;
            const char* src = (const char*)g_xpack8 +
                (((size_t)(tile * 8 + w) * NG + kq * 16) * 512 + (size_t)inner * 16);
            cpa16(dst + idx * 16, src);
        }
    }
    if (tid < 32) soff[tid] = g_off[tid];
    asm volatile("cp.async.commit_group;");
    asm volatile("cp.async.wait_group 0;" ::: "memory");
    __syncthreads();

    int warp = tid >> 5, lane = tid & 31;
    int q = lane & 3, r = lane >> 2;
    int tile16 = tile * 8 + warp;
    int rowA = tile16 * 16 + r, rowB = rowA + 8;

    const uint4* ap = (const uint4*)sa + warp * 512 + lane;

    float acc[4][4];
#pragma unroll
    for (int t = 0; t < 4; t++)
#pragma unroll
        for (int c = 0; c < 4; c++) acc[t][c] = 0.f;

    unsigned scol[4];
#pragma unroll
    for (int t = 0; t < 4; t++) scol[t] = (unsigned)((t * 8 + r) ^ (q << 3));

#pragma unroll
    for (int g = 0; g < 16; g++) {               // 16 groups of 32 k-cols
        uint4 a = ap[g * 32];                    // a0..a3 fragment regs (LDS.128)
        int w0 = (g * 8 + q) * 32;
        int w1 = (g * 8 + q + 4) * 32;
#pragma unroll
        for (int t = 0; t < 4; t++) {
            unsigned b0 = srp[w0 + scol[t]];
            unsigned b1 = srp[w1 + scol[t]];
            mma16832(acc[t], a.x, a.y, a.z, a.w, b0, b1);
        }
    }

    // publish my quarter's partials
    float* dst = g_part + (size_t)kq * N_ROWS * N_BINS;
#pragma unroll
    for (int t = 0; t < 4; t++) {
        int cb = t * 8 + 2 * q;
        *(float2*)(dst + (size_t)rowA * N_BINS + cb) = make_float2(acc[t][0], acc[t][1]);
        *(float2*)(dst + (size_t)rowB * N_BINS + cb) = make_float2(acc[t][2], acc[t][3]);
    }
    __threadfence();
    if (tid == 0) s_last = (int)atomicAdd(&g_tilecnt[tile], 1u);
    __syncthreads();
    if (s_last != NKQ - 1) return;    // earlier arrivals are done
    __threadfence();                  // make peers' partials visible

    // last-arriving quarter: add 3 peer partials (L2), subtract offset, sign
    unsigned mlo = 0u, mhi = 0u;
#pragma unroll
    for (int t = 0; t < 4; t++) {
        int cb = t * 8 + 2 * q;
        float sA0 = acc[t][0], sA1 = acc[t][1];
        float sB0 = acc[t][2], sB1 = acc[t][3];
#pragma unroll
        for (int o = 0; o < NKQ; o++) {
            if (o == kq) continue;
            const float* src = g_part + (size_t)o * N_ROWS * N_BINS;
            float2 pa = *(const float2*)(src + (size_t)rowA * N_BINS + cb);
            float2 pb = *(const float2*)(src + (size_t)rowB * N_BINS + cb);
            sA0 += pa.x; sA1 += pa.y;
            sB0 += pb.x; sB1 += pb.y;
        }
        float o0 = soff[cb], o1 = soff[cb + 1];
        mlo |= ((sA0 - o0) > 0.f ? 1u : 0u) << cb;
        mlo |= ((sA1 - o1) > 0.f ? 1u : 0u) << (cb + 1);
        mhi |= ((sB0 - o0) > 0.f ? 1u : 0u) << cb;
        mhi |= ((sB1 - o1) > 0.f ? 1u : 0u) << (cb + 1);
    }
    mlo |= __shfl_xor_sync(0xffffffffu, mlo, 1);
    mlo |= __shfl_xor_sync(0xffffffffu, mlo, 2);
    mhi |= __shfl_xor_sync(0xffffffffu, mhi, 1);
    mhi |= __shfl_xor_sync(0xffffffffu, mhi, 2);

    if (q == 0) {
        g_hash[rowA] = mlo;
        g_hash[rowB] = mhi;
        table_insert(rowA, mlo);
        table_insert(rowB, mhi);
    }
}

// ---------------------------------------------------------------------------
// Kernel 5: rewards. Unique keys -> 1.0; rare duplicates get exact rank.
// ---------------------------------------------------------------------------
__global__ void k_final(float* __restrict__ out) {
    int i = blockIdx.x * 128 + threadIdx.x;
    unsigned s = g_slot[i];
    float v = 1.0f;
    if (g_tcnt[s] != 1u) {
        unsigned long long my = ((unsigned long long)g_hash[i] << 6) | (unsigned long long)(i & 63);
        int c = 1;
        for (int j = 0; j < i; j++) {
            unsigned long long kj = ((unsigned long long)g_hash[j] << 6) | (unsigned long long)(j & 63);
            c += (kj == my) ? 1 : 0;
        }
        v = 1.0f / sqrtf((float)c);
    }
    out[i] = v;
}

// ---------------------------------------------------------------------------
// Launch
// ---------------------------------------------------------------------------
extern "C" void kernel_launch(void* const* d_in, const int* in_sizes, int n_in,
                              void* d_out, int out_size) {
    const float* x  = (const float*)d_in[0];
    const float* rp = (const float*)d_in[1];
    if (in_sizes[0] == N_FEAT * N_BINS) {   // defensive: swap if order differs
        const float* t = x; x = rp; rp = t;
    }
    float* out = (float*)d_out;

    cudaFuncSetAttribute(k_project, cudaFuncAttributeMaxDynamicSharedMemorySize, PROJ_SMEM);

    k_pre    <<<1280, 256>>>(x);
    k_stats  <<<64, 256>>>();
    k_scale  <<<65, 256>>>(rp);
    k_project<<<512, 256, PROJ_SMEM>>>();
    k_final  <<<128, 128>>>(out);
}

// round 10
// speedup vs baseline: 1.0120x; 1.0120x over previous
#include <cuda_runtime.h>
#include <cstdint>

// ---------------------------------------------------------------------------
// Problem constants
// ---------------------------------------------------------------------------
#define N_ROWS 16384      // 64 * 256
#define N_FEAT 2048
#define N_BINS 32
#define NSTRIPE 512
#define TBL 65536
#define NTILE 128                  // 128-row tiles
#define NKQ 4                      // K split into quarters (512 cols each)
#define NG 64                      // 32-col groups over full K
#define NT16 (N_ROWS / 16)         // 1024 16-row fragments
// k_project dynamic smem: RP quarter 16KB + A block 64KB + soff
#define PROJ_SMEM (16384 + 65536 + 128)

// ---------------------------------------------------------------------------
// Scratch (static device globals; no runtime allocation)
// ---------------------------------------------------------------------------
__device__ __align__(16) unsigned int g_xpack8[(size_t)NT16 * NG * 32 * 4]; // e4m3 x (32MB)
__device__ float              g_psum[NSTRIPE * N_FEAT];
__device__ float              g_psq [NSTRIPE * N_FEAT];
__device__ float              g_isig[N_FEAT];
__device__ float              g_m2  [N_FEAT];              // mean * isig
__device__ float              g_off [N_BINS];              // 256 * (m2 . RP)
__device__ __align__(16) unsigned int g_rppack8[512 * 32]; // e4m3x4 256*isig*RP, swizzled
__device__ float              g_part[NKQ * N_ROWS * N_BINS]; // split-K partials
__device__ unsigned int       g_tilecnt[NTILE];            // arrival counters
__device__ unsigned int       g_hash[N_ROWS];
__device__ unsigned int       g_slot[N_ROWS];
__device__ unsigned long long g_tkey[TBL];
__device__ unsigned int       g_tcnt[TBL];

// ---------------------------------------------------------------------------
// Helpers
// ---------------------------------------------------------------------------
__device__ __forceinline__ unsigned pack8x4(float f0, float f1, float f2, float f3) {
    unsigned d;
    asm("{\n\t"
        ".reg .b16 lo, hi;\n\t"
        "cvt.rn.satfinite.e4m3x2.f32 lo, %2, %1;\n\t"
        "cvt.rn.satfinite.e4m3x2.f32 hi, %4, %3;\n\t"
        "mov.b32 %0, {lo, hi};\n\t"
        "}" : "=r"(d) : "f"(f0), "f"(f1), "f"(f2), "f"(f3));
    return d;
}

__device__ __forceinline__ void mma16832(float* c,
                                         unsigned a0, unsigned a1, unsigned a2, unsigned a3,
                                         unsigned b0, unsigned b1) {
    asm volatile(
        "mma.sync.aligned.m16n8k32.row.col.f32.e4m3.e4m3.f32 "
        "{%0,%1,%2,%3}, {%4,%5,%6,%7}, {%8,%9}, {%0,%1,%2,%3};"
        : "+f"(c[0]), "+f"(c[1]), "+f"(c[2]), "+f"(c[3])
        : "r"(a0), "r"(a1), "r"(a2), "r"(a3), "r"(b0), "r"(b1));
}

__device__ __forceinline__ uint32_t smaddr(const void* p) {
    return (uint32_t)__cvta_generic_to_shared(p);
}

__device__ __forceinline__ void cpa16(uint32_t dst, const void* src) {
    asm volatile("cp.async.cg.shared.global [%0], [%1], 16;" :: "r"(dst), "l"(src));
}

__device__ __forceinline__ void table_insert(int i, unsigned h) {
    unsigned long long key = ((unsigned long long)h << 6) | (unsigned long long)(i & 63);
    unsigned long long m = key * 0x9E3779B97F4A7C15ULL;
    unsigned s = (unsigned)(m >> 48);   // 16-bit slot
    for (;;) {
        unsigned long long prev = atomicCAS(&g_tkey[s], ~0ULL, key);
        if (prev == ~0ULL || prev == key) {
            atomicAdd(&g_tcnt[s], 1u);
            g_slot[i] = s;
            return;
        }
        s = (s + 1) & (TBL - 1);
    }
}

// ---------------------------------------------------------------------------
// Kernel 1 (fused): column partial sums + e4m3 fragment pack + inits.
//   blocks [0,512): stats+pack. Block owns 32 rows (2 tile16) x all 2048 cols.
//     Thread (g = tid>>2, qp = tid&3) owns 8 cols: {g*32+4qp..+3, +16..+19};
//     per row-pair (rr, rr+8) it loads 4 float4 (full-sector 64B chunks) and
//     stores ONE uint4 fragment word (full-sector STG.128) at the exact R8
//     layout address: uint4[(tile16*NG+g)*32 + rr*4 + qp] =
//       {pack(rowA,k0..3), pack(rowB,k0..3), pack(rowA,k16..19), pack(rowB,k16..19)}
//   blocks [512,768): hash-table / counter init.
// ---------------------------------------------------------------------------
__global__ void k_pre(const float* __restrict__ x) {
    int b = blockIdx.x;
    if (b < 512) {
        int tid = threadIdx.x;
        int g = tid >> 2, qp = tid & 3;
        int f0 = g * 8 + qp;            // float4 slot, khalf=0 (k = 32g+4qp)
        int f1 = f0 + 4;                // float4 slot, khalf=1 (k = 32g+16+4qp)
        const float4* x4 = (const float4*)x;
        uint4* xp4 = (uint4*)g_xpack8;

        float s[8], qq[8];
#pragma unroll
        for (int j = 0; j < 8; j++) { s[j] = 0.f; qq[j] = 0.f; }

#pragma unroll
        for (int tt = 0; tt < 2; tt++) {
            int tile16 = b * 2 + tt;
            size_t rbaseA = (size_t)tile16 * 16 * 512;
            size_t wbase  = ((size_t)tile16 * NG + g) * 32 + qp;
#pragma unroll 2
            for (int rr = 0; rr < 8; rr++) {
                size_t rA = rbaseA + (size_t)rr * 512;
                size_t rB = rA + 8 * 512;
                float4 vA0 = x4[rA + f0];
                float4 vA1 = x4[rA + f1];
                float4 vB0 = x4[rB + f0];
                float4 vB1 = x4[rB + f1];

                s[0] += vA0.x + vB0.x; qq[0] += vA0.x*vA0.x + vB0.x*vB0.x;
                s[1] += vA0.y + vB0.y; qq[1] += vA0.y*vA0.y + vB0.y*vB0.y;
                s[2] += vA0.z + vB0.z; qq[2] += vA0.z*vA0.z + vB0.z*vB0.z;
                s[3] += vA0.w + vB0.w; qq[3] += vA0.w*vA0.w + vB0.w*vB0.w;
                s[4] += vA1.x + vB1.x; qq[4] += vA1.x*vA1.x + vB1.x*vB1.x;
                s[5] += vA1.y + vB1.y; qq[5] += vA1.y*vA1.y + vB1.y*vB1.y;
                s[6] += vA1.z + vB1.z; qq[6] += vA1.z*vA1.z + vB1.z*vB1.z;
                s[7] += vA1.w + vB1.w; qq[7] += vA1.w*vA1.w + vB1.w*vB1.w;

                uint4 w;
                w.x = pack8x4(vA0.x, vA0.y, vA0.z, vA0.w);
                w.y = pack8x4(vB0.x, vB0.y, vB0.z, vB0.w);
                w.z = pack8x4(vA1.x, vA1.y, vA1.z, vA1.w);
                w.w = pack8x4(vB1.x, vB1.y, vB1.z, vB1.w);
                xp4[wbase + (size_t)rr * 4] = w;
            }
        }
        int c0 = g * 32 + qp * 4;
        *(float4*)(g_psum + (size_t)b * N_FEAT + c0)      = make_float4(s[0], s[1], s[2], s[3]);
        *(float4*)(g_psum + (size_t)b * N_FEAT + c0 + 16) = make_float4(s[4], s[5], s[6], s[7]);
        *(float4*)(g_psq  + (size_t)b * N_FEAT + c0)      = make_float4(qq[0], qq[1], qq[2], qq[3]);
        *(float4*)(g_psq  + (size_t)b * N_FEAT + c0 + 16) = make_float4(qq[4], qq[5], qq[6], qq[7]);
    } else {
        int i = (b - 512) * 256 + threadIdx.x;
        g_tkey[i] = ~0ULL;
        g_tcnt[i] = 0u;
        if (b == 512 && threadIdx.x < NTILE) g_tilecnt[threadIdx.x] = 0u;
    }
}

// ---------------------------------------------------------------------------
// Kernel 2: finalize RunningMeanStd -> isig, mean*isig
// ---------------------------------------------------------------------------
__global__ void k_stats() {
    __shared__ float ss[8][32], sq[8][32];
    int c = threadIdx.x & 31, g = threadIdx.x >> 5;
    int col = blockIdx.x * 32 + c;
    float s = 0.f, q = 0.f;
    for (int st = g; st < NSTRIPE; st += 8) {
        s += g_psum[st * N_FEAT + col];
        q += g_psq [st * N_FEAT + col];
    }
    ss[g][c] = s; sq[g][c] = q;
    __syncthreads();
    if (g == 0) {
#pragma unroll
        for (int j = 1; j < 8; j++) { s += ss[j][c]; q += sq[j][c]; }
        const float n = 16384.0f;
        float bm = s / n;
        float bv = (q - bm * bm * n) / (n - 1.0f);       // unbiased variance
        const double nd = 16384.0, totd = 1e-4 + nd;
        float mean = bm * (float)(nd / totd);
        float m2v  = (1e-4f + bv * 16384.0f) + (bm * bm) * (float)(1e-4 * nd / totd);
        float var  = m2v / (float)totd;
        float isg  = 1.0f / sqrtf(var + 1e-8f);
        g_isig[col] = isg;
        g_m2[col]   = mean * isg;
    }
}

// ---------------------------------------------------------------------------
// Kernel 3: RP'' = 256*isig*RP packed e4m3x4 swizzled (blocks 0..63);
//           off[b] = 256 * sum_k m2[k]*RP[k,b] (block 64, deterministic).
// ---------------------------------------------------------------------------
__global__ void k_scale(const float* __restrict__ rp) {
    if (blockIdx.x < 64) {
        int idx = blockIdx.x * 256 + threadIdx.x;  // 0..16383
        int k4 = idx >> 5;                         // 4-col k word 0..511
        int n  = idx & 31;
        float f0 = rp[(4 * k4 + 0) * N_BINS + n] * g_isig[4 * k4 + 0] * 256.0f;
        float f1 = rp[(4 * k4 + 1) * N_BINS + n] * g_isig[4 * k4 + 1] * 256.0f;
        float f2 = rp[(4 * k4 + 2) * N_BINS + n] * g_isig[4 * k4 + 2] * 256.0f;
        float f3 = rp[(4 * k4 + 3) * N_BINS + n] * g_isig[4 * k4 + 3] * 256.0f;
        int scol = n ^ ((k4 & 3) << 3);
        g_rppack8[k4 * 32 + scol] = pack8x4(f0, f1, f2, f3);
    } else {
        __shared__ float red[8][32];
        int b = threadIdx.x & 31, part = threadIdx.x >> 5;   // 8 parts x 256 k
        float s = 0.f;
        for (int k = part * 256; k < part * 256 + 256; k++)
            s = fmaf(g_m2[k], rp[k * N_BINS + b], s);
        red[part][b] = s;
        __syncthreads();
        if (part == 0) {
#pragma unroll
            for (int j = 1; j < 8; j++) s += red[j][b];
            g_off[b] = s * 256.0f;
        }
    }
}

// ---------------------------------------------------------------------------
// Kernel 4: quarter-K e4m3 mma projection. cp.async stages the block's whole
// A working set (64KB) + RP quarter (16KB) into smem -> LDS.128 mainloop ->
// fp32 partials -> (last-arriving quarter per tile) combine + sign + insert.
//   512 blocks: tile = bid>>2 (128 rows), kq = bid&3.
// ---------------------------------------------------------------------------
__global__ void __launch_bounds__(256, 2) k_project() {
    extern __shared__ unsigned smem[];
    unsigned* srp = smem;                        // [0,4096) words: RP quarter
    unsigned* sa  = smem + 4096;                 // [4096,20480) words: A 64KB
    float* soff   = (float*)(smem + 20480);      // [32]
    __shared__ int s_last;

    int tile = blockIdx.x >> 2;
    int kq   = blockIdx.x & 3;
    int tid  = threadIdx.x;

    // stage RP quarter (1024 x 16B) via cp.async
    {
        const char* src = (const char*)(g_rppack8 + kq * 4096);
        uint32_t dst = smaddr(srp);
#pragma unroll
        for (int i = 0; i < 4; i++) {
            int idx = tid + i * 256;
            cpa16(dst + idx * 16, src + idx * 16);
        }
    }
    // stage A block (4096 x 16B): warp w's tile16 chunk is 8KB contiguous
    {
        uint32_t dst = smaddr(sa);
#pragma unroll
        for (int i = 0; i < 16; i++) {
            int idx = tid + i * 256;          // 0..4095 (16B units)
            int w = idx >> 9, inner = idx & 511;
            const char* src = (const char*)g_xpack8 +
                (((size_t)(tile * 8 + w) * NG + kq * 16) * 512 + (size_t)inner * 16);
            cpa16(dst + idx * 16, src);
        }
    }
    if (tid < 32) soff[tid] = g_off[tid];
    asm volatile("cp.async.commit_group;");
    asm volatile("cp.async.wait_group 0;" ::: "memory");
    __syncthreads();

    int warp = tid >> 5, lane = tid & 31;
    int q = lane & 3, r = lane >> 2;
    int tile16 = tile * 8 + warp;
    int rowA = tile16 * 16 + r, rowB = rowA + 8;

    const uint4* ap = (const uint4*)sa + warp * 512 + lane;

    float acc[4][4];
#pragma unroll
    for (int t = 0; t < 4; t++)
#pragma unroll
        for (int c = 0; c < 4; c++) acc[t][c] = 0.f;

    unsigned scol[4];
#pragma unroll
    for (int t = 0; t < 4; t++) scol[t] = (unsigned)((t * 8 + r) ^ (q << 3));

#pragma unroll
    for (int g = 0; g < 16; g++) {               // 16 groups of 32 k-cols
        uint4 a = ap[g * 32];                    // a0..a3 fragment regs (LDS.128)
        int w0 = (g * 8 + q) * 32;
        int w1 = (g * 8 + q + 4) * 32;
#pragma unroll
        for (int t = 0; t < 4; t++) {
            unsigned b0 = srp[w0 + scol[t]];
            unsigned b1 = srp[w1 + scol[t]];
            mma16832(acc[t], a.x, a.y, a.z, a.w, b0, b1);
        }
    }

    // publish my quarter's partials
    float* dst = g_part + (size_t)kq * N_ROWS * N_BINS;
#pragma unroll
    for (int t = 0; t < 4; t++) {
        int cb = t * 8 + 2 * q;
        *(float2*)(dst + (size_t)rowA * N_BINS + cb) = make_float2(acc[t][0], acc[t][1]);
        *(float2*)(dst + (size_t)rowB * N_BINS + cb) = make_float2(acc[t][2], acc[t][3]);
    }
    __threadfence();
    if (tid == 0) s_last = (int)atomicAdd(&g_tilecnt[tile], 1u);
    __syncthreads();
    if (s_last != NKQ - 1) return;    // earlier arrivals are done
    __threadfence();                  // make peers' partials visible

    // last-arriving quarter: add 3 peer partials (L2), subtract offset, sign
    unsigned mlo = 0u, mhi = 0u;
#pragma unroll
    for (int t = 0; t < 4; t++) {
        int cb = t * 8 + 2 * q;
        float sA0 = acc[t][0], sA1 = acc[t][1];
        float sB0 = acc[t][2], sB1 = acc[t][3];
#pragma unroll
        for (int o = 0; o < NKQ; o++) {
            if (o == kq) continue;
            const float* src = g_part + (size_t)o * N_ROWS * N_BINS;
            float2 pa = *(const float2*)(src + (size_t)rowA * N_BINS + cb);
            float2 pb = *(const float2*)(src + (size_t)rowB * N_BINS + cb);
            sA0 += pa.x; sA1 += pa.y;
            sB0 += pb.x; sB1 += pb.y;
        }
        float o0 = soff[cb], o1 = soff[cb + 1];
        mlo |= ((sA0 - o0) > 0.f ? 1u : 0u) << cb;
        mlo |= ((sA1 - o1) > 0.f ? 1u : 0u) << (cb + 1);
        mhi |= ((sB0 - o0) > 0.f ? 1u : 0u) << cb;
        mhi |= ((sB1 - o1) > 0.f ? 1u : 0u) << (cb + 1);
    }
    mlo |= __shfl_xor_sync(0xffffffffu, mlo, 1);
    mlo |= __shfl_xor_sync(0xffffffffu, mlo, 2);
    mhi |= __shfl_xor_sync(0xffffffffu, mhi, 1);
    mhi |= __shfl_xor_sync(0xffffffffu, mhi, 2);

    if (q == 0) {
        g_hash[rowA] = mlo;
        g_hash[rowB] = mhi;
        table_insert(rowA, mlo);
        table_insert(rowB, mhi);
    }
}

// ---------------------------------------------------------------------------
// Kernel 5: rewards. Unique keys -> 1.0; rare duplicates get exact rank.
// ---------------------------------------------------------------------------
__global__ void k_final(float* __restrict__ out) {
    int i = blockIdx.x * 128 + threadIdx.x;
    unsigned s = g_slot[i];
    float v = 1.0f;
    if (g_tcnt[s] != 1u) {
        unsigned long long my = ((unsigned long long)g_hash[i] << 6) | (unsigned long long)(i & 63);
        int c = 1;
        for (int j = 0; j < i; j++) {
            unsigned long long kj = ((unsigned long long)g_hash[j] << 6) | (unsigned long long)(j & 63);
            c += (kj == my) ? 1 : 0;
        }
        v = 1.0f / sqrtf((float)c);
    }
    out[i] = v;
}

// ---------------------------------------------------------------------------
// Launch
// ---------------------------------------------------------------------------
extern "C" void kernel_launch(void* const* d_in, const int* in_sizes, int n_in,
                              void* d_out, int out_size) {
    const float* x  = (const float*)d_in[0];
    const float* rp = (const float*)d_in[1];
    if (in_sizes[0] == N_FEAT * N_BINS) {   // defensive: swap if order differs
        const float* t = x; x = rp; rp = t;
    }
    float* out = (float*)d_out;

    cudaFuncSetAttribute(k_project, cudaFuncAttributeMaxDynamicSharedMemorySize, PROJ_SMEM);

    k_pre    <<<768, 256>>>(x);
    k_stats  <<<64, 256>>>();
    k_scale  <<<65, 256>>>(rp);
    k_project<<<512, 256, PROJ_SMEM>>>();
    k_final  <<<128, 128>>>(out);
}